// round 15
// baseline (speedup 1.0000x reference)
#include <cuda_runtime.h>
#include <math.h>

// Problem dims
#define N_   256
#define T_   128
#define D_   512
#define H_   1024
#define OUT_ 128

// LSTM-step GEMM tiling
#define BM 64      // batch rows per CTA
#define BH 32      // h-columns per CTA (x4 gates = 128 gate-cols)
#define BK 16      // k-depth per smem tile (double-buffered)

typedef unsigned long long u64;

// Persistent scratch. Re-zeroed by init_kernel on every replay.
__device__ float g_h[2][N_ * H_];   // ping-pong hidden state
__device__ float g_c[N_ * H_];      // cell state (in place)

// ---------------------------------------------------------------------------
__global__ void init_kernel() {
    int idx = blockIdx.x * blockDim.x + threadIdx.x;
    if (idx < N_ * H_) {
        g_h[0][idx] = 0.0f;
        g_c[idx]    = 0.0f;
    }
}

__device__ __forceinline__ float fsigmoid(float z) {
    return 1.0f / (1.0f + __expf(-z));
}
__device__ __forceinline__ float ftanh(float z) {
    return 1.0f - 2.0f / (__expf(2.0f * z) + 1.0f);
}

__device__ __forceinline__ u64 pack_f32x2(float lo, float hi) {
    u64 r;
    asm("mov.b64 %0, {%1, %2};" : "=l"(r) : "f"(lo), "f"(hi));
    return r;
}
__device__ __forceinline__ void unpack_f32x2(float& lo, float& hi, u64 v) {
    asm("mov.b64 {%0, %1}, %2;" : "=f"(lo), "=f"(hi) : "l"(v));
}
__device__ __forceinline__ void fma_f32x2(u64& d, u64 a, u64 b) {
    asm("fma.rn.f32x2 %0, %1, %2, %0;" : "+l"(d) : "l"(a), "l"(b));
}

// ---------------------------------------------------------------------------
// Fused LSTM step. Tile 64 rows x 128 gate-cols per CTA; grid (32,4) = 128
// CTAs, ONE per SM. 512 threads (16 warps, 4/SMSP) to fix the measured
// latency bound (occ was 12.5%, issue 33%): thread (tx 0..31, ty 0..15) owns
// rows 4ty..4ty+3 and gate-interleaved cols 4tx..4tx+3 = h-col (h0+tx) x all
// 4 gates -> 16 acc = 8 u64, fully thread-local cell update.
//
// Per warp per kk: A-frag = one 16B broadcast LDS.128 (1 cyc), B-frag = one
// LDS.128 (32 distinct segments, 4 cyc), 4 packs, 8 fma.f32x2. Per-SM/kk
// bounds: FMA 64 cyc, crossbar ~80, issue ~56/SMSP; 4 warps/SMSP hides LDS
// latency. Two-stage double buffer, one __syncthreads per K-tile.
// ---------------------------------------------------------------------------
__global__ __launch_bounds__(512)
void lstm_step_kernel(const float* __restrict__ x,     // [N, T, D]
                      const float* __restrict__ W_ih,  // [4H, D]
                      const float* __restrict__ W_hh,  // [4H, H]
                      const float* __restrict__ b_ih,  // [4H]
                      const float* __restrict__ b_hh,  // [4H]
                      int t)
{
    __shared__ __align__(16) float As[2][BK][BM + 4];   // row stride 68 = 17x16B
    __shared__ __align__(16) float Bs[2][BK][128 + 4];  // row stride 132 = 33x16B

    const int tid = threadIdx.x;
    const int tx  = tid & 31;            // h-col within tile
    const int ty  = tid >> 5;            // row group (0..15)
    const int h0  = blockIdx.x * BH;
    const int m0  = blockIdx.y * BM;

    const float* __restrict__ h_in  = g_h[t & 1];
    float* __restrict__       h_out = g_h[(t + 1) & 1];

    // acc2[i][q]: rows m0+4ty+i, packed cols (4tx+2q, 4tx+2q+1) = gates 2q,2q+1
    u64 acc2[4][2];
#pragma unroll
    for (int i = 0; i < 4; i++) {
        acc2[i][0] = 0ULL;
        acc2[i][1] = 0ULL;
    }

    // Fill assignments:
    // A tile 64x16 = 256 float4 -> threads 0..255, one each.
    const int a_row = (tid & 255) >> 2;      // 0..63 (only used when tid<256)
    const int a_kp  = (tid & 3) << 2;
    // B tile 128x16 = 512 float4 -> all 512 threads, one each.
    const int b_c   = tid >> 2;              // 0..127: c = 4*h_local + gate
    const int b_kp  = (tid & 3) << 2;
    const int b_R   = (b_c & 3) * H_ + h0 + (b_c >> 2);   // weight row

#pragma unroll 1
    for (int phase = 0; phase < 2; phase++) {
        const float* __restrict__ A = (phase == 0) ? (x + (long)t * D_) : h_in;
        const long  a_stride        = (phase == 0) ? (long)T_ * D_ : (long)H_;
        const float* __restrict__ W = (phase == 0) ? W_ih : W_hh;
        const int   Kdim            = (phase == 0) ? D_ : H_;
        const int   ktiles          = Kdim / BK;

        const float* a_src = A + (long)(m0 + a_row) * a_stride + a_kp;
        const float* b_src = W + (long)b_R * Kdim + b_kp;

        // Prologue: tile 0 -> buffer 0
        float4 pa = make_float4(0.f, 0.f, 0.f, 0.f);
        if (tid < 256) pa = *reinterpret_cast<const float4*>(a_src);
        float4 pb = *reinterpret_cast<const float4*>(b_src);
        int buf = 0;
        if (tid < 256) {
            As[buf][a_kp + 0][a_row] = pa.x;  As[buf][a_kp + 1][a_row] = pa.y;
            As[buf][a_kp + 2][a_row] = pa.z;  As[buf][a_kp + 3][a_row] = pa.w;
        }
        Bs[buf][b_kp + 0][b_c] = pb.x; Bs[buf][b_kp + 1][b_c] = pb.y;
        Bs[buf][b_kp + 2][b_c] = pb.z; Bs[buf][b_kp + 3][b_c] = pb.w;
        __syncthreads();

#pragma unroll 1
        for (int kt = 0; kt < ktiles; kt++) {
            const bool has_next = (kt + 1) < ktiles;
            if (has_next) {
                int ko = (kt + 1) * BK;
                if (tid < 256) pa = *reinterpret_cast<const float4*>(a_src + ko);
                pb = *reinterpret_cast<const float4*>(b_src + ko);
            }

#pragma unroll
            for (int kk = 0; kk < BK; kk++) {
                float4 a4 = *reinterpret_cast<const float4*>(&As[buf][kk][ty << 2]);
                ulonglong2 bv = *reinterpret_cast<const ulonglong2*>(&Bs[buf][kk][tx << 2]);
                u64 a0 = pack_f32x2(a4.x, a4.x);
                u64 a1 = pack_f32x2(a4.y, a4.y);
                u64 a2 = pack_f32x2(a4.z, a4.z);
                u64 a3 = pack_f32x2(a4.w, a4.w);
                fma_f32x2(acc2[0][0], a0, bv.x); fma_f32x2(acc2[0][1], a0, bv.y);
                fma_f32x2(acc2[1][0], a1, bv.x); fma_f32x2(acc2[1][1], a1, bv.y);
                fma_f32x2(acc2[2][0], a2, bv.x); fma_f32x2(acc2[2][1], a2, bv.y);
                fma_f32x2(acc2[3][0], a3, bv.x); fma_f32x2(acc2[3][1], a3, bv.y);
            }

            if (has_next) {
                int nb = buf ^ 1;
                if (tid < 256) {
                    As[nb][a_kp + 0][a_row] = pa.x;  As[nb][a_kp + 1][a_row] = pa.y;
                    As[nb][a_kp + 2][a_row] = pa.z;  As[nb][a_kp + 3][a_row] = pa.w;
                }
                Bs[nb][b_kp + 0][b_c] = pb.x; Bs[nb][b_kp + 1][b_c] = pb.y;
                Bs[nb][b_kp + 2][b_c] = pb.z; Bs[nb][b_kp + 3][b_c] = pb.w;
                buf = nb;
            }
            __syncthreads();
        }
    }

    // Epilogue: cols 4tx+j = gate j of h-col (h0+tx). acc2[i][0]=(i,f),
    // acc2[i][1]=(g,o). Single owner per element.
    const int h  = h0 + tx;
    const float bi = __ldg(b_ih + h)          + __ldg(b_hh + h);
    const float bf = __ldg(b_ih + H_ + h)     + __ldg(b_hh + H_ + h);
    const float bg = __ldg(b_ih + 2 * H_ + h) + __ldg(b_hh + 2 * H_ + h);
    const float bo = __ldg(b_ih + 3 * H_ + h) + __ldg(b_hh + 3 * H_ + h);
#pragma unroll
    for (int i = 0; i < 4; i++) {
        const int m = m0 + (ty << 2) + i;
        float vi, vf, vg, vo;
        unpack_f32x2(vi, vf, acc2[i][0]);
        unpack_f32x2(vg, vo, acc2[i][1]);

        float ig = fsigmoid(vi + bi);
        float fg = fsigmoid(vf + bf);
        float gg = ftanh   (vg + bg);
        float og = fsigmoid(vo + bo);

        const int idx = m * H_ + h;
        float c = fg * g_c[idx] + ig * gg;
        g_c[idx]   = c;
        h_out[idx] = og * ftanh(c);
    }
}

// ---------------------------------------------------------------------------
// Dense layer: C[M, Nc] = act(A[M, K] @ W[Nc, K]^T + b). 64x64 tiles, BK=32,
// 256 threads, 4x4 per-thread. a_is_h selects the persistent final h state.
// (<2% of total runtime.)
// ---------------------------------------------------------------------------
__global__ __launch_bounds__(256)
void dense_kernel(const float* __restrict__ A_in,
                  int a_is_h,
                  const float* __restrict__ W,   // [Nc, K]
                  const float* __restrict__ b,   // [Nc]
                  float* __restrict__ C,         // [M, Nc]
                  int Nc, int K, int do_relu)
{
    __shared__ __align__(16) float As[32][65];
    __shared__ __align__(16) float Bs[32][65];

    const float* __restrict__ A = a_is_h ? g_h[0] : A_in;

    const int tid = threadIdx.x;
    const int tx  = tid & 15;
    const int ty  = tid >> 4;
    const int n0  = blockIdx.x * 64;
    const int m0  = blockIdx.y * 64;

    float acc[4][4];
#pragma unroll
    for (int i = 0; i < 4; i++)
#pragma unroll
        for (int j = 0; j < 4; j++) acc[i][j] = 0.0f;

    for (int k0 = 0; k0 < K; k0 += 32) {
#pragma unroll
        for (int r = 0; r < 2; r++) {
            int idx = tid + 256 * r;
            int row = idx >> 3;
            int kp  = (idx & 7) << 2;
            float4 va = *reinterpret_cast<const float4*>(
                A + (long)(m0 + row) * K + k0 + kp);
            As[kp + 0][row] = va.x; As[kp + 1][row] = va.y;
            As[kp + 2][row] = va.z; As[kp + 3][row] = va.w;
            float4 vb = *reinterpret_cast<const float4*>(
                W + (long)(n0 + row) * K + k0 + kp);
            Bs[kp + 0][row] = vb.x; Bs[kp + 1][row] = vb.y;
            Bs[kp + 2][row] = vb.z; Bs[kp + 3][row] = vb.w;
        }
        __syncthreads();

#pragma unroll 8
        for (int kk = 0; kk < 32; kk++) {
            float a[4], bb[4];
#pragma unroll
            for (int i = 0; i < 4; i++) a[i]  = As[kk][ty + 16 * i];
#pragma unroll
            for (int j = 0; j < 4; j++) bb[j] = Bs[kk][tx + 16 * j];
#pragma unroll
            for (int i = 0; i < 4; i++)
#pragma unroll
                for (int j = 0; j < 4; j++) acc[i][j] += a[i] * bb[j];
        }
        __syncthreads();
    }

#pragma unroll
    for (int i = 0; i < 4; i++) {
        int m = m0 + ty + 16 * i;
#pragma unroll
        for (int j = 0; j < 4; j++) {
            int n   = n0 + tx + 16 * j;
            float v = acc[i][j] + __ldg(b + n);
            if (do_relu) v = fmaxf(v, 0.0f);
            C[(long)m * Nc + n] = v;
        }
    }
}

// ---------------------------------------------------------------------------
// Launcher: init -> 128 fused LSTM steps -> ReLU head -> output head.
// d_out layout: [0 : 256*128) = output, then [.. : +256*1024) = pre_output.
// ---------------------------------------------------------------------------
extern "C" void kernel_launch(void* const* d_in, const int* in_sizes, int n_in,
                              void* d_out, int out_size)
{
    const float* x    = (const float*)d_in[0];
    const float* W_ih = (const float*)d_in[1];
    const float* W_hh = (const float*)d_in[2];
    const float* b_ih = (const float*)d_in[3];
    const float* b_hh = (const float*)d_in[4];
    const float* W1   = (const float*)d_in[5];
    const float* b1   = (const float*)d_in[6];
    const float* W2   = (const float*)d_in[7];
    const float* b2   = (const float*)d_in[8];
    float* out = (float*)d_out;

    float* out_final = out;                  // [256, 128]
    float* out_pre   = out + N_ * OUT_;      // [256, 1024]

    init_kernel<<<(N_ * H_ + 255) / 256, 256>>>();

    for (int t = 0; t < T_; t++) {
        lstm_step_kernel<<<dim3(H_ / BH, N_ / BM), 512>>>(
            x, W_ih, W_hh, b_ih, b_hh, t);
    }

    // pre_output = relu(last_h @ W1^T + b1); last_h is g_h[0] (T even).
    dense_kernel<<<dim3(H_ / 64, N_ / 64), 256>>>(
        nullptr, /*a_is_h=*/1, W1, b1, out_pre, H_, H_, /*relu=*/1);

    // output = pre_output @ W2^T + b2
    dense_kernel<<<dim3(OUT_ / 64, N_ / 64), 256>>>(
        out_pre, /*a_is_h=*/0, W2, b2, out_final, OUT_, H_, /*relu=*/0);
}